// round 4
// baseline (speedup 1.0000x reference)
#include <cuda_runtime.h>
#include <cuda_bf16.h>
#include <cstddef>

// Problem constants (fixed by the dataset)
#define BATCH 64
#define LSEQ  512
#define DIN   256
#define HDIM  256
#define H3    768
#define ADIM  128
#define DEPTH 4
#define NROWS (LSEQ * BATCH)   // 32768

#define CLUSTER_NCTAS 8
#define ROWS_PER_CTA  112      // 896 / 8
#define NBAT          4        // batches per cluster
#define NCLU          16       // 64 / 4
#define SCAN_THREADS  896
#define GOUT_STRIDE   456      // 448 partials + 8 LN stats (floats), /4 = 114 float4
#define CLUBUF        (CLUSTER_NCTAS * GOUT_STRIDE)   // 3648 floats per parity buffer

// SMEM weight layout: two half-K blocks of 14800 floats (112 rows x 132 + 16 skew)
#define WBLK   14800
#define HBLK   528             // s_h half-block: 4 batches x 132
#define S_H_IDX(b, col) (((col) >> 7) * HBLK + (b) * 132 + ((col) & 127))

// ---------------- scratch (device globals; no allocation allowed) -------------
__device__ float g_hseq[(size_t)NROWS * HDIM];      // (L,B,H)
__device__ float g_xp  [(size_t)NROWS * H3];        // (L,B,3H)
__device__ float g_xa  [(size_t)NROWS * ADIM];      // (L,B,A)
__device__ float g_Ut2 [(size_t)(H3 + ADIM) * HDIM];// [U^T ; Ua1^T] 896x256
__device__ float g_hp  [(size_t)NCLU * 2 * CLUBUF]; // matvec exchange (double buffered)
__device__ unsigned char g_mask[BATCH * LSEQ];

// ---------------------------------- helpers ----------------------------------
__device__ __forceinline__ float warp_sum(float v) {
#pragma unroll
    for (int o = 16; o > 0; o >>= 1) v += __shfl_down_sync(0xffffffffu, v, o);
    return v;
}
__device__ __forceinline__ float sigmoidf(float x) { return 1.0f / (1.0f + expf(-x)); }

// packed f32x2 FMA (sm_103a; ptxas won't emit from C++ — PTX only)
__device__ __forceinline__ void fma2(unsigned long long& d, unsigned long long a,
                                     unsigned long long b) {
    asm("fma.rn.f32x2 %0, %1, %2, %0;" : "+l"(d) : "l"(a), "l"(b));
}
__device__ __forceinline__ unsigned long long pk(float lo, float hi) {
    unsigned long long r;
    asm("mov.b64 %0, {%1, %2};" : "=l"(r) : "f"(lo), "f"(hi));
    return r;
}
__device__ __forceinline__ float2 upk(unsigned long long v) {
    float2 r;
    asm("mov.b64 {%0, %1}, %2;" : "=f"(r.x), "=f"(r.y) : "l"(v));
    return r;
}

// ----------------- fused prep: weight transpose + mask copy -------------------
// blocks 0..895: g_Ut2 row k = U[:,k] (k<768) or Ua1[:,k-768]; block 896: mask.
__global__ void prep_fused(const float* __restrict__ U, const float* __restrict__ Ua1,
                           const unsigned char* __restrict__ m8) {
    int k = blockIdx.x;
    if (k < H3 + ADIM) {
        int i = threadIdx.x;  // 0..255
        float v = (k < H3) ? U[(size_t)i * H3 + k] : Ua1[(size_t)i * ADIM + (k - H3)];
        g_Ut2[(size_t)k * HDIM + i] = v;
    } else {
        __shared__ int mode;
        if (threadIdx.x == 0) {
            int nz = 0;
            for (int i = 0; i < 64; i++) nz |= m8[4 * i + 1] | m8[4 * i + 2] | m8[4 * i + 3];
            mode = nz ? 1 : 0;
        }
        __syncthreads();
        if (mode) {
            for (int i = threadIdx.x; i < BATCH * LSEQ; i += blockDim.x)
                g_mask[i] = m8[i] ? 1 : 0;
        } else {
            const int* m32 = (const int*)m8;
            for (int i = threadIdx.x; i < BATCH * LSEQ; i += blockDim.x)
                g_mask[i] = m32[i] ? 1 : 0;
        }
    }
}

// ------------------------------- tiled SGEMM (f32x2) --------------------------
template <bool REMAP>
__global__ void __launch_bounds__(256) sgemm_kernel(
    const float* __restrict__ A, const float* __restrict__ Bm,
    const float* __restrict__ bias, float* __restrict__ C, int N) {
    const int K = 256;
    __shared__ __align__(16) float Ast[16][68];   // [kk][row]
    __shared__ __align__(16) float Bs[16][64];
    int t  = threadIdx.x;
    int m0 = blockIdx.y * 64;
    int n0 = blockIdx.x * 64;
    int ty = t >> 4, tx = t & 15;

    unsigned long long acc2[4][2];
#pragma unroll
    for (int i = 0; i < 4; i++) { acc2[i][0] = 0ull; acc2[i][1] = 0ull; }

    int ar = t >> 2;
    int ak = (t & 3) * 4;
    int arow = m0 + ar;
    const float* Aptr;
    if (REMAP) {
        int b = arow & 63, l = arow >> 6;
        Aptr = A + ((size_t)b * LSEQ + l) * K;
    } else {
        Aptr = A + (size_t)arow * K;
    }
    int bk = t >> 4;
    int bn = (t & 15) * 4;

    for (int k0 = 0; k0 < K; k0 += 16) {
        float4 av = *(const float4*)(Aptr + k0 + ak);
        Ast[ak + 0][ar] = av.x;
        Ast[ak + 1][ar] = av.y;
        Ast[ak + 2][ar] = av.z;
        Ast[ak + 3][ar] = av.w;
        *(float4*)(&Bs[bk][bn]) = *(const float4*)(Bm + (size_t)(k0 + bk) * N + n0 + bn);
        __syncthreads();
#pragma unroll
        for (int kk = 0; kk < 16; kk++) {
            float4 a  = *(const float4*)(&Ast[kk][ty * 4]);
            float4 bb = *(const float4*)(&Bs[kk][tx * 4]);
            unsigned long long b01 = pk(bb.x, bb.y), b23 = pk(bb.z, bb.w);
            unsigned long long ax = pk(a.x, a.x), ay = pk(a.y, a.y);
            unsigned long long az = pk(a.z, a.z), aw = pk(a.w, a.w);
            fma2(acc2[0][0], ax, b01); fma2(acc2[0][1], ax, b23);
            fma2(acc2[1][0], ay, b01); fma2(acc2[1][1], ay, b23);
            fma2(acc2[2][0], az, b01); fma2(acc2[2][1], az, b23);
            fma2(acc2[3][0], aw, b01); fma2(acc2[3][1], aw, b23);
        }
        __syncthreads();
    }
#pragma unroll
    for (int i = 0; i < 4; i++) {
        int row = m0 + ty * 4 + i;
        float2 v01 = upk(acc2[i][0]), v23 = upk(acc2[i][1]);
        float4 v;
        v.x = v01.x; v.y = v01.y; v.z = v23.x; v.w = v23.y;
        if (bias) {
            v.x += bias[n0 + tx * 4 + 0];
            v.y += bias[n0 + tx * 4 + 1];
            v.z += bias[n0 + tx * 4 + 2];
            v.w += bias[n0 + tx * 4 + 3];
        }
        *(float4*)(&C[(size_t)row * N + n0 + tx * 4]) = v;
    }
}

// ------------------------- rowwise LayerNorm over 768 ------------------------
__global__ void __launch_bounds__(256) ln_rows(float* __restrict__ xp,
                                               const float* __restrict__ gammas,
                                               const float* __restrict__ betas) {
    int r = blockIdx.x;
    float* row = xp + (size_t)r * H3;
    int t = threadIdx.x;
    float v0 = row[t], v1 = row[t + 256], v2 = row[t + 512];
    float s = v0 + v1 + v2;
    float q = v0 * v0 + v1 * v1 + v2 * v2;
    __shared__ float rs[8], rq[8];
    __shared__ float s_mu, s_rstd;
    float ws = warp_sum(s), wq = warp_sum(q);
    if ((t & 31) == 0) { rs[t >> 5] = ws; rq[t >> 5] = wq; }
    __syncthreads();
    if (t == 0) {
        float S = 0.f, Q = 0.f;
#pragma unroll
        for (int i = 0; i < 8; i++) { S += rs[i]; Q += rq[i]; }
        float mu  = S * (1.0f / 768.0f);
        float var = Q * (1.0f / 768.0f) - mu * mu;
        s_mu = mu;
        s_rstd = rsqrtf(var + 1e-5f);
    }
    __syncthreads();
    float mu = s_mu, rstd = s_rstd;
    row[t]       = gammas[t]       * (v0 - mu) * rstd + betas[t];
    row[t + 256] = gammas[t + 256] * (v1 - mu) * rstd + betas[t + 256];
    row[t + 512] = gammas[t + 512] * (v2 - mu) * rstd + betas[t + 512];
}

// --------------------- cluster-resident sequential scan -----------------------
// 16 clusters x 8 CTAs; cluster owns 4 batches; CTA rank r holds rows 112r..+111
// of [U^T;Ua1^T] in SMEM (split-half skewed layout, conflict-free LDS.128).
// All 896 threads do half-dots via fma.rn.f32x2; LN stats folded into phase A;
// one cluster barrier per step; xp/xa prefetched for l+1 during phase B.
__global__ void __cluster_dims__(CLUSTER_NCTAS, 1, 1) __launch_bounds__(SCAN_THREADS, 1)
scan2_kernel(int d,
             const float* __restrict__ bg,
             const float* __restrict__ gammas,
             const float* __restrict__ betas,
             const float* __restrict__ ba1,
             const float* __restrict__ Wa2,
             const float* __restrict__ ba2,
             float* __restrict__ out, int out_size) {
    extern __shared__ __align__(16) float sm[];
    float* Wsm   = sm;                          // 2*14800 = 29600
    float* s_h   = Wsm  + 2 * WBLK;             // 2*528   = 1056
    float* s_hp  = s_h  + 2 * HBLK;             // 896*5   = 4480
    float* s_xp  = s_hp + 896 * 5;              // 2*4*768 = 6144
    float* s_xa  = s_xp + 2 * NBAT * H3;        // 2*4*128 = 1024
    float* c_bg  = s_xa + 2 * NBAT * ADIM;      // 768
    float* c_g1  = c_bg + H3;                   // 768
    float* c_b1  = c_g1 + H3;                   // 768
    float* c_ba1 = c_b1 + H3;                   // 128
    float* c_wa2 = c_ba1 + ADIM;                // 256
    float* s_lnred = c_wa2 + 2 * ADIM;          // 28*8 = 224
    float* s_red = s_lnred + 224;               // 64
    float* s_stat= s_red + 64;                  // 8
    unsigned char* s_mask = (unsigned char*)(s_stat + 8); // 4*512 bytes

    const int t    = threadIdx.x;
    const int rank = blockIdx.x & (CLUSTER_NCTAS - 1);
    const int clu  = blockIdx.x >> 3;
    const int b0   = clu * NBAT;
    const int wid  = t >> 5, lane = t & 31;

    // ---- load weight slice into split-half skewed layout ----
    {
        const float4* src = (const float4*)(g_Ut2 + (size_t)(ROWS_PER_CTA * rank) * HDIM);
        for (int i = t; i < ROWS_PER_CTA * 64; i += SCAN_THREADS) {
            int row = i >> 6, c4 = i & 63;
            float4 v = src[(size_t)row * 64 + c4];
            int half = c4 >> 5, k4 = c4 & 31;
            *(float4*)(Wsm + half * WBLK + row * 132 + k4 * 4) = v;
        }
    }
    for (int i = t; i < H3; i += SCAN_THREADS) {
        c_bg[i] = bg[i];
        c_g1[i] = gammas[H3 + i];
        c_b1[i] = betas[H3 + i];
    }
    if (t < ADIM)     c_ba1[t] = ba1[t];
    if (t < 2 * ADIM) c_wa2[t] = Wa2[t];
    for (int i = t; i < NBAT * LSEQ; i += SCAN_THREADS)
        s_mask[i] = g_mask[(b0 + (i >> 9)) * LSEQ + (i & 511)];
    for (int i = t; i < 2 * HBLK; i += SCAN_THREADS) s_h[i] = 0.0f;
    // prefetch xp/xa for step 0 into buffer 0
    for (int i = t; i < NBAT * (H3 / 4); i += SCAN_THREADS) {        // 768 float4
        int bb = i / 192, c4 = i % 192;
        *(float4*)(s_xp + bb * H3 + c4 * 4) =
            *(const float4*)(g_xp + ((size_t)b0 + bb) * H3 + c4 * 4);
    }
    if (t < NBAT * (ADIM / 4)) {                                      // 128 float4
        int bb = t >> 5, c4 = t & 31;
        *(float4*)(s_xa + bb * ADIM + c4 * 4) =
            *(const float4*)(g_xa + ((size_t)b0 + bb) * ADIM + c4 * 4);
    }
    __syncthreads();

    const bool write_full = (out_size >= 409600);
    // matvec mapping: pair p = t>>1 -> (wrow, wb); half = t&1 -> K range
    const int p = t >> 1, half = t & 1;
    const int wrow = p >> 2, wb = p & 3;
    const float4* wp = (const float4*)(Wsm + half * WBLK + wrow * 132);
    const bool ln_inrange = (rank * ROWS_PER_CTA + wrow) < H3;
    // phase-B gather mapping
    const int rank_r = t / 112, wrow_r = t - rank_r * 112;
    const int grow_r = rank_r * ROWS_PER_CTA + wrow_r;

    float* hp_base = g_hp + (size_t)clu * (2 * CLUBUF);
    const float ba2_0 = ba2[0], ba2_1 = ba2[1];

    for (int l = 0; l < LSEQ; ++l) {
        const int par = l & 1;
        float* gout = hp_base + par * CLUBUF;

        // ---- phase A: half-dot matvec (all 896 threads, f32x2 FMA) ----
        {
            const float4* hq = (const float4*)(s_h + half * HBLK + wb * 132);
            unsigned long long a0 = 0ull, a1 = 0ull, a2 = 0ull, a3 = 0ull;
#pragma unroll
            for (int i = 0; i < 32; i += 2) {
                float4 w0 = wp[i],     h0 = hq[i];
                float4 w1 = wp[i + 1], h1 = hq[i + 1];
                fma2(a0, pk(w0.x, w0.y), pk(h0.x, h0.y));
                fma2(a1, pk(w0.z, w0.w), pk(h0.z, h0.w));
                fma2(a2, pk(w1.x, w1.y), pk(h1.x, h1.y));
                fma2(a3, pk(w1.z, w1.w), pk(h1.z, h1.w));
            }
            float2 s0 = upk(a0), s1 = upk(a1), s2 = upk(a2), s3 = upk(a3);
            float dot = ((s0.x + s0.y) + (s1.x + s1.y)) + ((s2.x + s2.y) + (s3.x + s3.y));
            dot += __shfl_xor_sync(0xffffffffu, dot, 1);   // combine halves
            if (!half) gout[rank * GOUT_STRIDE + p] = dot;
            // LN partial sums (even lanes only; rows >= 768 excluded)
            float v  = (!half && ln_inrange) ? dot : 0.0f;
            float vq = v * v;
            v  += __shfl_xor_sync(0xffffffffu, v, 8);
            v  += __shfl_xor_sync(0xffffffffu, v, 16);
            vq += __shfl_xor_sync(0xffffffffu, vq, 8);
            vq += __shfl_xor_sync(0xffffffffu, vq, 16);
            if (lane < 8 && !(lane & 1)) {
                s_lnred[wid * 8 + (lane >> 1)]     = v;
                s_lnred[wid * 8 + 4 + (lane >> 1)] = vq;
            }
        }
        __syncthreads();
        if (t < 8) {   // reduce LN partials over 28 warps, append to gout
            float acc = 0.0f;
#pragma unroll
            for (int w = 0; w < 28; w++) acc += s_lnred[w * 8 + t];
            gout[rank * GOUT_STRIDE + 448 + t] = acc;
        }

        // one cluster barrier per step (release partials / acquire peers')
        asm volatile("barrier.cluster.arrive.aligned;" ::: "memory");
        asm volatile("barrier.cluster.wait.aligned;" ::: "memory");

        // ---- phase B: gather hp + stats ----
        {
            float4 v = __ldcv(((const float4*)gout) + rank_r * (GOUT_STRIDE / 4) + wrow_r);
            float* dst = s_hp + grow_r * 5;
            dst[0] = v.x; dst[1] = v.y; dst[2] = v.z; dst[3] = v.w;
        }
        if (t < 64) {
            int r8 = t >> 3, s8 = t & 7;
            s_red[t] = __ldcv(gout + r8 * GOUT_STRIDE + 448 + s8);
        }
        __syncthreads();
        if (t < 8) {   // warp 0: stats across 8 ranks, then mu/rstd
            float S = 0.0f;
#pragma unroll
            for (int r8 = 0; r8 < 8; r8++) S += s_red[t + 8 * r8];
            float Sq = __shfl_sync(0x000000ffu, S, (t + 4) & 7);
            if (t < 4) {
                float mu  = S * (1.0f / 768.0f);
                float var = Sq * (1.0f / 768.0f) - mu * mu;
                s_stat[t]     = mu;
                s_stat[4 + t] = rsqrtf(var + 1e-5f);
            }
        }
        __syncthreads();

        // ---- gates (t<512, 2 items) | xp/xa prefetch for l+1 (t>=512) ----
        const float* xpb_all = s_xp + par * (NBAT * H3);
        if (t < 512) {
            int col = t & 255;
#pragma unroll
            for (int rep = 0; rep < 2; rep++) {
                int bb = (t >> 8) + rep * 2;
                float mu = s_stat[bb], rs = s_stat[4 + bb];
                float hp0 = (s_hp[col * 5 + bb]         - mu) * rs * c_g1[col]       + c_b1[col];
                float hp1 = (s_hp[(col + 256) * 5 + bb] - mu) * rs * c_g1[col + 256] + c_b1[col + 256];
                float hp2 = (s_hp[(col + 512) * 5 + bb] - mu) * rs * c_g1[col + 512] + c_b1[col + 512];
                const float* xpb = xpb_all + bb * H3;
                float r  = sigmoidf(xpb[col]       + hp0     + c_bg[col]);
                float z  = sigmoidf(xpb[col + 256] + hp1     + c_bg[col + 256]);
                float hh = tanhf   (xpb[col + 512] + r * hp2 + c_bg[col + 512]);
                float hold = s_h[S_H_IDX(bb, col)];
                float hn = z * hold + (1.0f - z) * hh;
                float ho = s_mask[bb * LSEQ + l] ? hn : hold;
                s_h[S_H_IDX(bb, col)] = ho;
                if (rank == bb) {
                    g_hseq[((size_t)l * BATCH + b0 + bb) * HDIM + col] = ho;
                    if (d == DEPTH - 1 && l == LSEQ - 1 && out_size >= BATCH * HDIM)
                        out[(b0 + bb) * HDIM + col] = ho;
                }
            }
        } else {
            int u = t - 512;                          // 384 helpers
            int ln2 = (l + 1 < LSEQ) ? l + 1 : l;
            const size_t grow = (size_t)ln2 * BATCH + b0;
            float* xpd = s_xp + ((l + 1) & 1) * (NBAT * H3);
            for (int i = u; i < NBAT * (H3 / 4); i += 384) {
                int bb = i / 192, c4 = i % 192;
                *(float4*)(xpd + bb * H3 + c4 * 4) =
                    *(const float4*)(g_xp + (grow + bb) * H3 + c4 * 4);
            }
            if (u < NBAT * (ADIM / 4)) {
                int bb = u >> 5, c4 = u & 31;
                *(float4*)(s_xa + ((l + 1) & 1) * (NBAT * ADIM) + bb * ADIM + c4 * 4) =
                    *(const float4*)(g_xa + (grow + bb) * ADIM + c4 * 4);
            }
        }

        // ---- action head (t<512): tanh + dot with Wa2 ----
        if (t < 512) {
            int bb = t >> 7, k = t & 127;
            float a = tanhf(s_xa[par * (NBAT * ADIM) + bb * ADIM + k] +
                            s_hp[(H3 + k) * 5 + bb] + c_ba1[k]);
            float p0 = warp_sum(a * c_wa2[2 * k]);
            float p1 = warp_sum(a * c_wa2[2 * k + 1]);
            if ((t & 31) == 0) { s_red[32 + (t >> 5)] = p0; s_red[48 + (t >> 5)] = p1; }
        }
        __syncthreads();
        if (t < 4) {
            float l0 = s_red[32 + 4 * t] + s_red[33 + 4 * t] + s_red[34 + 4 * t] + s_red[35 + 4 * t] + ba2_0;
            float l1 = s_red[48 + 4 * t] + s_red[49 + 4 * t] + s_red[50 + 4 * t] + s_red[51 + 4 * t] + ba2_1;
            unsigned char mt  = s_mask[t * LSEQ + l];
            unsigned char act = ((l1 > l0) && mt) ? 1 : 0;
            s_mask[t * LSEQ + l] = act;                    // next-depth mask (local)
            if (rank == 4 + t) {
                g_mask[(b0 + t) * LSEQ + l] = act;
                if (write_full) {
                    float m = fmaxf(l0, l1);
                    float e0 = expf(l0 - m), e1 = expf(l1 - m);
                    float inv = 1.0f / (e0 + e1);
                    size_t ai = (size_t)BATCH * HDIM + ((size_t)((b0 + t) * DEPTH + d)) * LSEQ + l;
                    out[ai] = act ? 1.0f : 0.0f;
                    size_t pi = (size_t)BATCH * HDIM + (size_t)BATCH * DEPTH * LSEQ +
                                (((size_t)((b0 + t) * DEPTH + d)) * LSEQ + l) * 2;
                    out[pi]     = e0 * inv;
                    out[pi + 1] = e1 * inv;
                }
            }
        }
        __syncthreads();   // protect s_h / s_mask / s_red before next step
    }
}

// --------------------------------- launcher ----------------------------------
extern "C" void kernel_launch(void* const* d_in, const int* in_sizes, int n_in,
                              void* d_out, int out_size) {
    const float* x     = (const float*)d_in[0];
    const unsigned char* mask = (const unsigned char*)d_in[1];
    const float* W_emb = (const float*)d_in[2];
    const float* b_emb = (const float*)d_in[3];
    const float* W     = (const float*)d_in[4];
    const float* U     = (const float*)d_in[5];
    const float* bgate = (const float*)d_in[6];
    const float* Wa1   = (const float*)d_in[7];
    const float* Ua1   = (const float*)d_in[8];
    const float* ba1   = (const float*)d_in[9];
    const float* Wa2   = (const float*)d_in[10];
    const float* ba2   = (const float*)d_in[11];
    const float* gammas = (const float*)d_in[12];
    const float* betas  = (const float*)d_in[13];
    float* out = (float*)d_out;

    float *hseq, *xp, *xa;
    cudaGetSymbolAddress((void**)&hseq, g_hseq);
    cudaGetSymbolAddress((void**)&xp, g_xp);
    cudaGetSymbolAddress((void**)&xa, g_xa);

    const int scan_smem =
        (2 * WBLK + 2 * HBLK + 896 * 5 + 2 * NBAT * H3 + 2 * NBAT * ADIM +
         3 * H3 + ADIM + 2 * ADIM + 224 + 64 + 8) * 4 + NBAT * LSEQ;
    static int attr_done = 0;
    if (!attr_done) {
        cudaFuncSetAttribute(scan2_kernel, cudaFuncAttributeMaxDynamicSharedMemorySize, scan_smem);
        attr_done = 1;
    }

    // launch order chosen so launch index 5 == first scan (ncu -s 5 -c 1)
    prep_fused<<<H3 + ADIM + 1, HDIM>>>(U, Ua1, mask);                          // 0
    sgemm_kernel<true><<<dim3(HDIM / 64, NROWS / 64), 256>>>(x, W_emb, b_emb, hseq, HDIM); // 1

    for (int d = 0; d < DEPTH; d++) {
        sgemm_kernel<false><<<dim3(H3 / 64, NROWS / 64), 256>>>(hseq, W, nullptr, xp, H3);     // 2
        sgemm_kernel<false><<<dim3(ADIM / 64, NROWS / 64), 256>>>(hseq, Wa1, nullptr, xa, ADIM); // 3
        ln_rows<<<NROWS, 256>>>(xp, gammas, betas);                                             // 4
        scan2_kernel<<<NCLU * CLUSTER_NCTAS, SCAN_THREADS, scan_smem>>>(
            d, bgate, gammas, betas, ba1, Wa2, ba2, out, out_size);                             // 5
    }
}

// round 5
// speedup vs baseline: 1.1595x; 1.1595x over previous
#include <cuda_runtime.h>
#include <cuda_bf16.h>
#include <cstddef>

// Problem constants (fixed by the dataset)
#define BATCH 64
#define LSEQ  512
#define DIN   256
#define HDIM  256
#define H3    768
#define ADIM  128
#define DEPTH 4
#define NROWS (LSEQ * BATCH)   // 32768
#define NCAT  896              // 768 xp + 128 xa

#define CLUSTER_NCTAS 8
#define ROWS_PER_CTA  112      // 896 / 8
#define NBAT          4        // batches per cluster
#define NCLU          16       // 64 / 4
#define SCAN_THREADS  896
#define GOUT_STRIDE   448      // floats per rank record
#define CLUBUF        (CLUSTER_NCTAS * GOUT_STRIDE)   // 3584 floats per parity

// SMEM weight layout: row r occupies 72 float4 (8 kq-blocks of 9 float4: 8 data + 1 pad)
#define WROW_F4  72
// hT layout: 8 blocks of 33 float4 (32 data + 1 pad) = 264 float4
#define HT_F4(k)        ((((k) >> 5) * 33) + ((k) & 31))
#define HT_FLT(k, b)    ((((k) >> 5) * 132) + (((k) & 31) * 4) + (b))

// ---------------- scratch (device globals; no allocation allowed) -------------
__device__ float g_hseq[(size_t)NROWS * HDIM];      // (L,B,H)
__device__ float g_xpa [(size_t)NROWS * NCAT];      // (L,B,896): xp|xa
__device__ float g_Wcat[(size_t)DIN * NCAT];        // [W | Wa1] (256x896)
__device__ float g_Ut2 [(size_t)(H3 + ADIM) * HDIM];// [U^T ; Ua1^T] 896x256
__device__ float g_hp  [(size_t)NCLU * 2 * CLUBUF]; // matvec exchange (double buffered)
__device__ unsigned char g_mask[BATCH * LSEQ];

// ---------------------------------- helpers ----------------------------------
__device__ __forceinline__ float warp_sum(float v) {
#pragma unroll
    for (int o = 16; o > 0; o >>= 1) v += __shfl_down_sync(0xffffffffu, v, o);
    return v;
}
__device__ __forceinline__ float sigmoidf(float x) { return 1.0f / (1.0f + expf(-x)); }

// packed f32x2 FMA (sm_103a; PTX-only)
__device__ __forceinline__ void fma2(unsigned long long& d, unsigned long long a,
                                     unsigned long long b) {
    asm("fma.rn.f32x2 %0, %1, %2, %0;" : "+l"(d) : "l"(a), "l"(b));
}
__device__ __forceinline__ unsigned long long pk(float lo, float hi) {
    unsigned long long r;
    asm("mov.b64 %0, {%1, %2};" : "=l"(r) : "f"(lo), "f"(hi));
    return r;
}
__device__ __forceinline__ float2 upk(unsigned long long v) {
    float2 r;
    asm("mov.b64 {%0, %1}, %2;" : "=f"(r.x), "=f"(r.y) : "l"(v));
    return r;
}

// ----------------- fused prep: Ut2 transpose + Wcat + mask --------------------
__global__ void prep_fused(const float* __restrict__ U, const float* __restrict__ Ua1,
                           const float* __restrict__ W, const float* __restrict__ Wa1,
                           const unsigned char* __restrict__ m8) {
    int k = blockIdx.x;
    if (k < H3 + ADIM) {
        int i = threadIdx.x;  // 0..255
        float v = (k < H3) ? U[(size_t)i * H3 + k] : Ua1[(size_t)i * ADIM + (k - H3)];
        g_Ut2[(size_t)k * HDIM + i] = v;
    } else if (k < H3 + ADIM + DIN) {
        int r = k - (H3 + ADIM);    // 0..255
        for (int n = threadIdx.x; n < NCAT; n += blockDim.x)
            g_Wcat[(size_t)r * NCAT + n] =
                (n < H3) ? W[(size_t)r * H3 + n] : Wa1[(size_t)r * ADIM + (n - H3)];
    } else {
        __shared__ int mode;
        if (threadIdx.x == 0) {
            int nz = 0;
            for (int i = 0; i < 64; i++) nz |= m8[4 * i + 1] | m8[4 * i + 2] | m8[4 * i + 3];
            mode = nz ? 1 : 0;
        }
        __syncthreads();
        if (mode) {
            for (int i = threadIdx.x; i < BATCH * LSEQ; i += blockDim.x)
                g_mask[i] = m8[i] ? 1 : 0;
        } else {
            const int* m32 = (const int*)m8;
            for (int i = threadIdx.x; i < BATCH * LSEQ; i += blockDim.x)
                g_mask[i] = m32[i] ? 1 : 0;
        }
    }
}

// ------------------------------- tiled SGEMM (f32x2) --------------------------
template <bool REMAP>
__global__ void __launch_bounds__(256) sgemm_kernel(
    const float* __restrict__ A, const float* __restrict__ Bm,
    const float* __restrict__ bias, float* __restrict__ C, int N) {
    const int K = 256;
    __shared__ __align__(16) float Ast[16][68];
    __shared__ __align__(16) float Bs[16][64];
    int t  = threadIdx.x;
    int m0 = blockIdx.y * 64;
    int n0 = blockIdx.x * 64;
    int ty = t >> 4, tx = t & 15;

    unsigned long long acc2[4][2];
#pragma unroll
    for (int i = 0; i < 4; i++) { acc2[i][0] = 0ull; acc2[i][1] = 0ull; }

    int ar = t >> 2;
    int ak = (t & 3) * 4;
    int arow = m0 + ar;
    const float* Aptr;
    if (REMAP) {
        int b = arow & 63, l = arow >> 6;
        Aptr = A + ((size_t)b * LSEQ + l) * K;
    } else {
        Aptr = A + (size_t)arow * K;
    }
    int bk = t >> 4;
    int bn = (t & 15) * 4;

    for (int k0 = 0; k0 < K; k0 += 16) {
        float4 av = *(const float4*)(Aptr + k0 + ak);
        Ast[ak + 0][ar] = av.x;
        Ast[ak + 1][ar] = av.y;
        Ast[ak + 2][ar] = av.z;
        Ast[ak + 3][ar] = av.w;
        *(float4*)(&Bs[bk][bn]) = *(const float4*)(Bm + (size_t)(k0 + bk) * N + n0 + bn);
        __syncthreads();
#pragma unroll
        for (int kk = 0; kk < 16; kk++) {
            float4 a  = *(const float4*)(&Ast[kk][ty * 4]);
            float4 bb = *(const float4*)(&Bs[kk][tx * 4]);
            unsigned long long b01 = pk(bb.x, bb.y), b23 = pk(bb.z, bb.w);
            unsigned long long ax = pk(a.x, a.x), ay = pk(a.y, a.y);
            unsigned long long az = pk(a.z, a.z), aw = pk(a.w, a.w);
            fma2(acc2[0][0], ax, b01); fma2(acc2[0][1], ax, b23);
            fma2(acc2[1][0], ay, b01); fma2(acc2[1][1], ay, b23);
            fma2(acc2[2][0], az, b01); fma2(acc2[2][1], az, b23);
            fma2(acc2[3][0], aw, b01); fma2(acc2[3][1], aw, b23);
        }
        __syncthreads();
    }
#pragma unroll
    for (int i = 0; i < 4; i++) {
        int row = m0 + ty * 4 + i;
        float2 v01 = upk(acc2[i][0]), v23 = upk(acc2[i][1]);
        float4 v;
        v.x = v01.x; v.y = v01.y; v.z = v23.x; v.w = v23.y;
        if (bias) {
            v.x += bias[n0 + tx * 4 + 0];
            v.y += bias[n0 + tx * 4 + 1];
            v.z += bias[n0 + tx * 4 + 2];
            v.w += bias[n0 + tx * 4 + 3];
        }
        *(float4*)(&C[(size_t)row * N + n0 + tx * 4]) = v;
    }
}

// --------------------- cluster-resident sequential scan -----------------------
// 16 clusters x 8 CTAs; cluster owns 4 batches. CTA rank r holds rows 112r..+111
// of [U^T;Ua1^T] in SMEM. Phase A: thread (row,kq) loads each weight float4 ONCE
// and FMAs against transposed h (all 4 batches) -> 4x less weight LDS. xp/xa
// prefetch issued between cluster arrive/wait; xp-LN stats for step l+1 computed
// by helper warps off the critical path; gates normalize xp lazily.
__global__ void __cluster_dims__(CLUSTER_NCTAS, 1, 1) __launch_bounds__(SCAN_THREADS, 1)
scan2_kernel(int d,
             const float* __restrict__ bg,
             const float* __restrict__ gammas,
             const float* __restrict__ betas,
             const float* __restrict__ ba1,
             const float* __restrict__ Wa2,
             const float* __restrict__ ba2,
             float* __restrict__ out, int out_size) {
    extern __shared__ __align__(16) float sm[];
    float* Wsm   = sm;                              // 112*288 = 32256
    float* s_hT  = Wsm  + ROWS_PER_CTA * WROW_F4 * 4; // 264*4 = 1056
    float* s_hp  = s_hT + 1056;                     // 896*5  = 4480
    float* s_xpa = s_hp + 896 * 5;                  // 2*4*896= 7168
    float* c_g0  = s_xpa + 2 * NBAT * NCAT;         // 768
    float* c_b0  = c_g0 + H3;                       // 768
    float* c_g1  = c_b0 + H3;                       // 768
    float* c_b1  = c_g1 + H3;                       // 768
    float* c_bg  = c_b1 + H3;                       // 768
    float* c_ba1 = c_bg + H3;                       // 128
    float* c_wa2 = c_ba1 + ADIM;                    // 256
    float* s_red = c_wa2 + 2 * ADIM;                // 64
    float* s_stat= s_red + 64;                      // 8
    float* s_xscr= s_stat + 8;                      // 24 (12 helper warps x2)
    float* s_xst = s_xscr + 24;                     // 16 (2 buffers x (mu[4],rs[4]))
    unsigned char* s_mask = (unsigned char*)(s_xst + 16); // 4*512 bytes

    const int t    = threadIdx.x;
    const int rank = blockIdx.x & (CLUSTER_NCTAS - 1);
    const int clu  = blockIdx.x >> 3;
    const int b0   = clu * NBAT;

    // ---- load weight slice: (row, kq-block) padded layout ----
    {
        const float4* src = (const float4*)(g_Ut2 + (size_t)(ROWS_PER_CTA * rank) * HDIM);
        float4* dst = (float4*)Wsm;
        for (int i = t; i < ROWS_PER_CTA * 64; i += SCAN_THREADS) {
            int row = i >> 6, c4 = i & 63;
            dst[row * WROW_F4 + (c4 >> 3) * 9 + (c4 & 7)] = src[(size_t)row * 64 + c4];
        }
    }
    for (int i = t; i < H3; i += SCAN_THREADS) {
        c_g0[i] = gammas[i];
        c_b0[i] = betas[i];
        c_g1[i] = gammas[H3 + i];
        c_b1[i] = betas[H3 + i];
        c_bg[i] = bg[i];
    }
    if (t < ADIM)     c_ba1[t] = ba1[t];
    if (t < 2 * ADIM) c_wa2[t] = Wa2[t];
    for (int i = t; i < NBAT * LSEQ; i += SCAN_THREADS)
        s_mask[i] = g_mask[(b0 + (i >> 9)) * LSEQ + (i & 511)];
    for (int i = t; i < 1056; i += SCAN_THREADS) s_hT[i] = 0.0f;

    // prefetch xpa for step 0 into buffer 0 (one float4 per thread)
    const int pf_bb = t / 224, pf_c4 = t - 224 * (t / 224);
    {
        float4 v = *((const float4*)g_xpa + ((size_t)b0 + pf_bb) * 224 + pf_c4);
        ((float4*)s_xpa)[pf_bb * 224 + pf_c4] = v;
    }
    __syncthreads();

    // prologue: xp-LN stats for step 0 (buffer 0)
    if (t >= 512) {
        int u = t - 512, bb = u / 96, q = u - 96 * bb;
        const float* xr = s_xpa + bb * NCAT;
        float s = 0.f, qq = 0.f;
#pragma unroll
        for (int j = 0; j < 8; j++) { float v = xr[q + 96 * j]; s += v; qq += v * v; }
        s = warp_sum(s); qq = warp_sum(qq);
        if (((t - 512) & 31) == 0) { int w = u >> 5; s_xscr[w * 2] = s; s_xscr[w * 2 + 1] = qq; }
    }
    __syncthreads();
    if (t >= 8 && t < 12) {
        int bb = t - 8;
        float S = 0.f, Q = 0.f;
#pragma unroll
        for (int j = 0; j < 3; j++) { S += s_xscr[(bb * 3 + j) * 2]; Q += s_xscr[(bb * 3 + j) * 2 + 1]; }
        float mu = S * (1.0f / 768.0f), var = Q * (1.0f / 768.0f) - mu * mu;
        s_xst[bb] = mu; s_xst[4 + bb] = rsqrtf(var + 1e-5f);
    }
    __syncthreads();

    const bool write_full = (out_size >= 409600);
    const int r_  = t >> 3, kq = t & 7;
    const float4* wf = (const float4*)Wsm + r_ * WROW_F4 + kq * 9;
    const float4* ht = (const float4*)s_hT;

    float* hp_base = g_hp + (size_t)clu * (2 * CLUBUF);
    const float ba2_0 = ba2[0], ba2_1 = ba2[1];

    for (int l = 0; l < LSEQ; ++l) {
        const int par = l & 1, nxt = par ^ 1;
        float* gout = hp_base + par * CLUBUF;

        // ---- phase A: matvec, weights loaded once, 4 batches per FMA pair ----
        {
            unsigned long long acc01 = 0ull, acc23 = 0ull;
#pragma unroll
            for (int i = 0; i < 8; i++) {
                float4 w  = wf[i];
                float4 h0 = ht[kq * 33 + i * 4 + 0];
                float4 h1 = ht[kq * 33 + i * 4 + 1];
                float4 h2 = ht[kq * 33 + i * 4 + 2];
                float4 h3 = ht[kq * 33 + i * 4 + 3];
                fma2(acc01, pk(w.x, w.x), pk(h0.x, h0.y)); fma2(acc23, pk(w.x, w.x), pk(h0.z, h0.w));
                fma2(acc01, pk(w.y, w.y), pk(h1.x, h1.y)); fma2(acc23, pk(w.y, w.y), pk(h1.z, h1.w));
                fma2(acc01, pk(w.z, w.z), pk(h2.x, h2.y)); fma2(acc23, pk(w.z, w.z), pk(h2.z, h2.w));
                fma2(acc01, pk(w.w, w.w), pk(h3.x, h3.y)); fma2(acc23, pk(w.w, w.w), pk(h3.z, h3.w));
            }
            float2 v01 = upk(acc01), v23 = upk(acc23);
            float d0 = v01.x, d1 = v01.y, d2 = v23.x, d3 = v23.y;
#pragma unroll
            for (int m = 1; m < 8; m <<= 1) {
                d0 += __shfl_xor_sync(0xffffffffu, d0, m);
                d1 += __shfl_xor_sync(0xffffffffu, d1, m);
                d2 += __shfl_xor_sync(0xffffffffu, d2, m);
                d3 += __shfl_xor_sync(0xffffffffu, d3, m);
            }
            if (kq == 0) {
                float4 o; o.x = d0; o.y = d1; o.z = d2; o.w = d3;
                ((float4*)gout)[rank * ROWS_PER_CTA + r_] = o;
            }
        }

        // ---- prefetch xpa for step l+1 (independent), hidden in barrier skew ----
        const int lp = (l + 1 < LSEQ) ? l + 1 : l;
        float4 pf = *((const float4*)g_xpa +
                      ((size_t)lp * BATCH + b0 + pf_bb) * 224 + pf_c4);

        asm volatile("barrier.cluster.arrive.aligned;" ::: "memory");
        asm volatile("barrier.cluster.wait.aligned;" ::: "memory");

        // ---- phase B: gather hp from peers; store prefetch ----
        {
            float4 v = __ldcv((const float4*)gout + t);
            float* dst = s_hp + t * 5;
            dst[0] = v.x; dst[1] = v.y; dst[2] = v.z; dst[3] = v.w;
        }
        ((float4*)(s_xpa + nxt * (NBAT * NCAT)))[pf_bb * 224 + pf_c4] = pf;
        __syncthreads();

        // LN stats over hp rows 0..767 (t<512) | xp stats for l+1 (t>=512)
        if (t < 512) {
            int bb = t >> 7, q = t & 127;
            float s = 0.f, qq = 0.f;
#pragma unroll
            for (int j = 0; j < 6; j++) {
                float v = s_hp[(q + 128 * j) * 5 + bb];
                s += v; qq += v * v;
            }
            s = warp_sum(s); qq = warp_sum(qq);
            if ((t & 31) == 0) { s_red[t >> 5] = s; s_red[16 + (t >> 5)] = qq; }
        } else {
            int u = t - 512, bb = u / 96, q = u - 96 * bb;
            const float* xr = s_xpa + nxt * (NBAT * NCAT) + bb * NCAT;
            float s = 0.f, qq = 0.f;
#pragma unroll
            for (int j = 0; j < 8; j++) { float v = xr[q + 96 * j]; s += v; qq += v * v; }
            s = warp_sum(s); qq = warp_sum(qq);
            if ((u & 31) == 0) { int w = u >> 5; s_xscr[w * 2] = s; s_xscr[w * 2 + 1] = qq; }
        }
        __syncthreads();
        if (t < 4) {
            float S = s_red[4 * t] + s_red[4 * t + 1] + s_red[4 * t + 2] + s_red[4 * t + 3];
            float Q = s_red[16 + 4 * t] + s_red[17 + 4 * t] + s_red[18 + 4 * t] + s_red[19 + 4 * t];
            float mu  = S * (1.0f / 768.0f);
            float var = Q * (1.0f / 768.0f) - mu * mu;
            s_stat[t]     = mu;
            s_stat[4 + t] = rsqrtf(var + 1e-5f);
        } else if (t >= 8 && t < 12) {
            int bb = t - 8;
            float S = 0.f, Q = 0.f;
#pragma unroll
            for (int j = 0; j < 3; j++) { S += s_xscr[(bb * 3 + j) * 2]; Q += s_xscr[(bb * 3 + j) * 2 + 1]; }
            float mu = S * (1.0f / 768.0f), var = Q * (1.0f / 768.0f) - mu * mu;
            s_xst[nxt * 8 + bb] = mu; s_xst[nxt * 8 + 4 + bb] = rsqrtf(var + 1e-5f);
        }
        __syncthreads();

        // ---- gates + action head (t<512) ----
        if (t < 512) {
            int col = t & 255;
#pragma unroll
            for (int rep = 0; rep < 2; rep++) {
                int bb = (t >> 8) + rep * 2;
                float mu = s_stat[bb], rs = s_stat[4 + bb];
                float mux = s_xst[par * 8 + bb], rsx = s_xst[par * 8 + 4 + bb];
                const float* xr = s_xpa + par * (NBAT * NCAT) + bb * NCAT;
                float x0 = c_g0[col]       * (xr[col]       - mux) * rsx + c_b0[col];
                float x1 = c_g0[col + 256] * (xr[col + 256] - mux) * rsx + c_b0[col + 256];
                float x2 = c_g0[col + 512] * (xr[col + 512] - mux) * rsx + c_b0[col + 512];
                float hp0 = (s_hp[col * 5 + bb]         - mu) * rs * c_g1[col]       + c_b1[col];
                float hp1 = (s_hp[(col + 256) * 5 + bb] - mu) * rs * c_g1[col + 256] + c_b1[col + 256];
                float hp2 = (s_hp[(col + 512) * 5 + bb] - mu) * rs * c_g1[col + 512] + c_b1[col + 512];
                float r  = sigmoidf(x0 + hp0     + c_bg[col]);
                float z  = sigmoidf(x1 + hp1     + c_bg[col + 256]);
                float hh = tanhf   (x2 + r * hp2 + c_bg[col + 512]);
                float hold = s_hT[HT_FLT(col, bb)];
                float hn = z * hold + (1.0f - z) * hh;
                float ho = s_mask[bb * LSEQ + l] ? hn : hold;
                s_hT[HT_FLT(col, bb)] = ho;
                if (rank == bb) {
                    g_hseq[((size_t)l * BATCH + b0 + bb) * HDIM + col] = ho;
                    if (d == DEPTH - 1 && l == LSEQ - 1 && out_size >= BATCH * HDIM)
                        out[(b0 + bb) * HDIM + col] = ho;
                }
            }
            // action head
            int bb = t >> 7, k = t & 127;
            float a = tanhf(s_xpa[par * (NBAT * NCAT) + bb * NCAT + H3 + k] +
                            s_hp[(H3 + k) * 5 + bb] + c_ba1[k]);
            float p0 = warp_sum(a * c_wa2[2 * k]);
            float p1 = warp_sum(a * c_wa2[2 * k + 1]);
            if ((t & 31) == 0) { s_red[32 + (t >> 5)] = p0; s_red[48 + (t >> 5)] = p1; }
        }
        __syncthreads();
        if (t < 4) {
            float l0 = s_red[32 + 4 * t] + s_red[33 + 4 * t] + s_red[34 + 4 * t] + s_red[35 + 4 * t] + ba2_0;
            float l1 = s_red[48 + 4 * t] + s_red[49 + 4 * t] + s_red[50 + 4 * t] + s_red[51 + 4 * t] + ba2_1;
            unsigned char mt  = s_mask[t * LSEQ + l];
            unsigned char act = ((l1 > l0) && mt) ? 1 : 0;
            s_mask[t * LSEQ + l] = act;                    // next-depth mask (local)
            if (rank == 4 + t) {
                g_mask[(b0 + t) * LSEQ + l] = act;
                if (write_full) {
                    float m = fmaxf(l0, l1);
                    float e0 = expf(l0 - m), e1 = expf(l1 - m);
                    float inv = 1.0f / (e0 + e1);
                    size_t ai = (size_t)BATCH * HDIM + ((size_t)((b0 + t) * DEPTH + d)) * LSEQ + l;
                    out[ai] = act ? 1.0f : 0.0f;
                    size_t pi = (size_t)BATCH * HDIM + (size_t)BATCH * DEPTH * LSEQ +
                                (((size_t)((b0 + t) * DEPTH + d)) * LSEQ + l) * 2;
                    out[pi]     = e0 * inv;
                    out[pi + 1] = e1 * inv;
                }
            }
        }
        __syncthreads();   // protect s_hT / s_mask / s_red before next step
    }
}

// --------------------------------- launcher ----------------------------------
extern "C" void kernel_launch(void* const* d_in, const int* in_sizes, int n_in,
                              void* d_out, int out_size) {
    const float* x     = (const float*)d_in[0];
    const unsigned char* mask = (const unsigned char*)d_in[1];
    const float* W_emb = (const float*)d_in[2];
    const float* b_emb = (const float*)d_in[3];
    const float* W     = (const float*)d_in[4];
    const float* U     = (const float*)d_in[5];
    const float* bgate = (const float*)d_in[6];
    const float* Wa1   = (const float*)d_in[7];
    const float* Ua1   = (const float*)d_in[8];
    const float* ba1   = (const float*)d_in[9];
    const float* Wa2   = (const float*)d_in[10];
    const float* ba2   = (const float*)d_in[11];
    const float* gammas = (const float*)d_in[12];
    const float* betas  = (const float*)d_in[13];
    float* out = (float*)d_out;

    float *hseq, *xpa, *wcat;
    cudaGetSymbolAddress((void**)&hseq, g_hseq);
    cudaGetSymbolAddress((void**)&xpa, g_xpa);
    cudaGetSymbolAddress((void**)&wcat, g_Wcat);

    const int scan_smem =
        (ROWS_PER_CTA * WROW_F4 * 4 + 1056 + 896 * 5 + 2 * NBAT * NCAT +
         5 * H3 + ADIM + 2 * ADIM + 64 + 8 + 24 + 16) * 4 + NBAT * LSEQ;
    static int attr_done = 0;
    if (!attr_done) {
        cudaFuncSetAttribute(scan2_kernel, cudaFuncAttributeMaxDynamicSharedMemorySize, scan_smem);
        attr_done = 1;
    }

    // our launches: 0 prep, 1 embed, 2 gemm896, 3 scan, ... -> scan at global idx 5
    prep_fused<<<H3 + ADIM + DIN + 1, HDIM>>>(U, Ua1, W, Wa1, mask);
    sgemm_kernel<true><<<dim3(HDIM / 64, NROWS / 64), 256>>>(x, W_emb, b_emb, hseq, HDIM);

    for (int d = 0; d < DEPTH; d++) {
        sgemm_kernel<false><<<dim3(NCAT / 64, NROWS / 64), 256>>>(hseq, wcat, nullptr, xpa, NCAT);
        scan2_kernel<<<NCLU * CLUSTER_NCTAS, SCAN_THREADS, scan_smem>>>(
            d, bgate, gammas, betas, ba1, Wa2, ba2, out, out_size);
    }
}